// round 12
// baseline (speedup 1.0000x reference)
#include <cuda_runtime.h>
#include <cuda_bf16.h>
#include <cstdint>

#define BNtok 65536
#define Dh    512
#define Kcb   1024
#define DSc   256

#define MARGIN_H 1e-3f      // bf16 HMMA coarse margin (validated R4)
#define MARGIN_D 2.5e-3f    // int8 dp4a coarse margin (validated R5/R10)
#define CAP    16
#define SWQ    (1.0f / 130048.0f)   // W quant scale: (1/1024)/127

// ---------------- device scratch -------------------------------------------
// bf16 W codes 0..767: [s][qt 24][chunk 4][32 codes x 128B] (4KB chunks)
__device__ __align__(16) uint8_t  g_whi[(size_t)2 * 24 * 16384];
// int8 W codes 768..1023: [s][qt 4][kc 64][64 codes x 4B]
__device__ __align__(16) uint32_t g_wt[2 * 4 * 64 * 64];
__device__ float  g_wsq[2 * Kcb];
__device__ int    g_ids[2 * BNtok];
__device__ double g_loss;

// ---------------- helpers --------------------------------------------------
#define SWZ(o) ((o) ^ (((o) >> 3) & 0x70))

static __device__ __forceinline__ uint32_t smem_u32(const void* p) {
    uint32_t a;
    asm("{ .reg .u64 t; cvta.to.shared.u64 t, %1; cvt.u32.u64 %0, t; }" : "=r"(a) : "l"(p));
    return a;
}

#define LDSM_X4(r0, r1, r2, r3, addr) \
    asm volatile("ldmatrix.sync.aligned.m8n8.x4.shared.b16 {%0,%1,%2,%3}, [%4];" \
        : "=r"(r0), "=r"(r1), "=r"(r2), "=r"(r3) : "r"(addr))

#define MMA16816(d, a0, a1, a2, a3, b0, b1) \
    asm volatile("mma.sync.aligned.m16n8k16.row.col.f32.bf16.bf16.f32 " \
        "{%0,%1,%2,%3}, {%4,%5,%6,%7}, {%8,%9}, {%0,%1,%2,%3};" \
        : "+f"((d)[0]), "+f"((d)[1]), "+f"((d)[2]), "+f"((d)[3]) \
        : "r"(a0), "r"(a1), "r"(a2), "r"(a3), "r"(b0), "r"(b1))

#define CP_ASYNC16(saddr, gptr) \
    asm volatile("cp.async.cg.shared.global [%0], [%1], 16;" :: "r"(saddr), "l"(gptr))
#define CP_COMMIT() asm volatile("cp.async.commit_group;" ::: "memory")

#define LDS128(v, addr) \
    asm volatile("ld.shared.v4.u32 {%0,%1,%2,%3}, [%4];" \
        : "=r"((v).x), "=r"((v).y), "=r"((v).z), "=r"((v).w) : "r"(addr))

static __device__ __forceinline__ uint32_t pack2bf(float a, float b) {
    uint32_t lo = __bfloat16_as_ushort(__float2bfloat16_rn(a));
    uint32_t hi = __bfloat16_as_ushort(__float2bfloat16_rn(b));
    return lo | (hi << 16);
}
static __device__ __forceinline__ uint32_t pack4s8(int a, int b, int c, int d) {
    return (uint32_t)(a & 0xFF) | ((uint32_t)(b & 0xFF) << 8) |
           ((uint32_t)(c & 0xFF) << 16) | ((uint32_t)(d & 0xFF) << 24);
}
static __device__ __forceinline__ int q8(float v, float inv) {
    int q = __float2int_rn(v * inv);
    return max(-127, min(127, q));
}

// ---------------- smem layout (bytes) --------------------------------------
#define XOFF   0         // A bf16: 4 chunks x 16384 = 65536
#define XTO    65536     // x int8 transposed+rotated: 64 x 512 = 32768
#define BOFF   98304     // HMMA B stages: 2 x 16384 = 32768
#define WTO    131072    // dp4a W: 4 qt x 16384 = 65536
#define WSQO   196608    // 1024 f32
#define CANDO  200704    // 128 x CAP u16
#define SCNTO  204800    // 128 int
#define SXO    205312    // 128 f32
#define SMEM_SZ 205824

// ---------------------------------------------------------------------------
// prep: W -> (bf16 swizzled tiles | int8 packed) + w_sq + zero loss.
// grid 256 x 256; one warp per code for wsq.
// ---------------------------------------------------------------------------
__global__ void prep_kernel(const float* __restrict__ W) {
    int gid = blockIdx.x * 256 + threadIdx.x;
    if (gid == 0) g_loss = 0.0;
    const float4* W4 = (const float4*)W;
    const float inv = 130048.0f;

    #pragma unroll
    for (int r = 0; r < 2; r++) {
        int fid  = gid * 2 + r;            // 0..131071
        int code = fid >> 6;               // 0..2047
        int q    = fid & 63;               // float4 idx (dims 4q..4q+3)
        float4 v = W4[(size_t)code * 64 + q];
        int kk = code & 1023;
        int s  = code >> 10;
        if (kk < 768) {
            int qt = kk >> 5, k = kk & 31;
            int chunk = q >> 4, qq = q & 15;
            uint8_t* base = g_whi + ((size_t)((s * 24 + qt) * 4 + chunk)) * 4096;
            uint32_t off = SWZ((uint32_t)(k * 128 + qq * 8));
            *(uint2*)(base + off) = make_uint2(pack2bf(v.x, v.y), pack2bf(v.z, v.w));
        } else {
            int qt = (kk - 768) >> 6, c = (kk - 768) & 63;
            g_wt[((s * 4 + qt) * 64 + q) * 64 + c] =
                pack4s8(q8(v.x, inv), q8(v.y, inv), q8(v.z, inv), q8(v.w, inv));
        }
    }

    int code = gid >> 5;
    int lane = gid & 31;
    float s = 0.f;
    #pragma unroll
    for (int r = 0; r < 2; r++) {
        float4 v = W4[(size_t)code * 64 + lane + r * 32];
        s += v.x * v.x + v.y * v.y + v.z * v.z + v.w * v.w;
    }
    #pragma unroll
    for (int o = 16; o > 0; o >>= 1) s += __shfl_xor_sync(0xffffffffu, s, o);
    if (lane == 0) g_wsq[code] = s;
}

// ---------------------------------------------------------------------------
// fused dual-pipe kernel. grid = 1024 (512 token-tiles x 2 slices), 384 thr.
// warps 0-7:  bf16 HMMA over codes 0..767  (16 tokens each)
// warps 8-11: int8 dp4a over codes 768..1023 (32 tokens each)
// ---------------------------------------------------------------------------
__global__ void __launch_bounds__(384, 1)
vq_kernel(const float* __restrict__ h, const float* __restrict__ W,
          float* __restrict__ out) {
    extern __shared__ __align__(1024) uint8_t smem[];
    const uint32_t sb = smem_u32(smem);

    const int tid = threadIdx.x;
    const int wid = tid >> 5;
    const int lid = tid & 31;
    const int r4  = lid >> 2;
    const int q4  = lid & 3;
    const int blk = blockIdx.x;
    const int s   = blk >> 9;
    const int m0  = (blk & 511) * 128;

    float*    swsq  = (float*)(smem + WSQO);
    uint16_t* candp = (uint16_t*)(smem + CANDO);
    int*      scnt  = (int*)(smem + SCNTO);
    float*    sxs   = (float*)(smem + SXO);

    if (tid < 128) scnt[tid] = 0;
    #pragma unroll
    for (int i = 0; i < 3; i++) {
        int idx = i * 384 + tid;
        if (idx < Kcb) swsq[idx] = g_wsq[s * Kcb + idx];
    }

    const float4* h4 = (const float4*)h;

    if (wid < 8) {
        // ---- x processing: bf16 A (swizzled) + int8 XT (rotated) + scales --
        for (int j = 0; j < 16; j++) {
            const int trow = wid * 16 + j;
            const int m    = m0 + trow;
            float4 v0 = h4[(size_t)m * (Dh / 4) + s * (DSc / 4) + lid];       // dims 4lid..
            float4 v1 = h4[(size_t)m * (Dh / 4) + s * (DSc / 4) + 32 + lid];  // dims 128+4lid..
            float mx = fmaxf(fmaxf(fmaxf(fabsf(v0.x), fabsf(v0.y)), fmaxf(fabsf(v0.z), fabsf(v0.w))),
                             fmaxf(fmaxf(fabsf(v1.x), fabsf(v1.y)), fmaxf(fabsf(v1.z), fabsf(v1.w))));
            #pragma unroll
            for (int o = 16; o > 0; o >>= 1)
                mx = fmaxf(mx, __shfl_xor_sync(0xffffffffu, mx, o));
            float inv = (mx > 0.f) ? (127.0f / mx) : 0.f;
            if (lid == 0) sxs[trow] = 2.0f * (mx / 127.0f) * SWQ;
            // bf16 A
            *(uint2*)(smem + XOFF + (lid >> 4) * 16384 + SWZ((uint32_t)(trow * 128 + (lid & 15) * 8)))
                = make_uint2(pack2bf(v0.x, v0.y), pack2bf(v0.z, v0.w));
            *(uint2*)(smem + XOFF + (2 + (lid >> 4)) * 16384 + SWZ((uint32_t)(trow * 128 + (lid & 15) * 8)))
                = make_uint2(pack2bf(v1.x, v1.y), pack2bf(v1.z, v1.w));
            // int8 XT: kc = lid and lid+32, row rotation (kc&31)*16
            uint32_t p0 = pack4s8(q8(v0.x, inv), q8(v0.y, inv), q8(v0.z, inv), q8(v0.w, inv));
            uint32_t p1 = pack4s8(q8(v1.x, inv), q8(v1.y, inv), q8(v1.z, inv), q8(v1.w, inv));
            *(uint32_t*)(smem + XTO + lid * 512 + ((trow * 4 + (lid & 31) * 16) & 511)) = p0;
            *(uint32_t*)(smem + XTO + (lid + 32) * 512 + ((trow * 4 + (lid & 31) * 16) & 511)) = p1;
        }
        // prefetch HMMA B qt 0,1 (16KB each, 256 threads -> 4 cp.async each)
        #pragma unroll
        for (int p = 0; p < 2; p++) {
            const uint8_t* src = g_whi + ((size_t)(s * 24 + p)) * 16384 + tid * 16;
            uint32_t dst = sb + BOFF + p * 16384 + tid * 16;
            #pragma unroll
            for (int i = 0; i < 4; i++) CP_ASYNC16(dst + i * 4096, src + i * 4096);
            CP_COMMIT();
        }
    } else {
        // dp4a warps: load all 4 WT tiles (64KB / 128 threads = 32 each)
        int t128 = tid - 256;
        const uint8_t* src = (const uint8_t*)g_wt + (size_t)s * 65536 + t128 * 16;
        uint32_t dst = sb + WTO + t128 * 16;
        #pragma unroll
        for (int i = 0; i < 32; i++) CP_ASYNC16(dst + i * 2048, src + i * 2048);
        CP_COMMIT();
    }
    __syncthreads();   // XT/sxs/A visible; everyone's cp.async committed

    if (wid < 8) {
        // ================= HMMA path: codes 0..767, 24 qtiles of 32 ========
        const int arow = wid * 16 + (lid & 7) + ((lid & 8) ? 8 : 0);
        const uint32_t aBase = sb + XOFF + (uint32_t)arow * 128;
        const uint32_t akhi  = (lid & 16) ? 16u : 0u;
        const uint32_t sxA   = (uint32_t)(arow & 7) << 4;
        const int brow = (lid & 7) + ((lid & 16) ? 8 : 0);
        const uint32_t bkhi  = (lid & 8) ? 16u : 0u;
        const uint32_t sxB   = (uint32_t)(brow & 7) << 4;
        const uint32_t brOff = (uint32_t)brow * 128;

        float vminA = 1e30f, vminB = 1e30f;
        const int tokA = wid * 16 + r4;
        const int tokB = tokA + 8;

        for (int qt = 0; qt < 24; qt++) {
            if (qt < 23) asm volatile("cp.async.wait_group 1;" ::: "memory");
            else         asm volatile("cp.async.wait_group 0;" ::: "memory");
            asm volatile("bar.sync 1, 256;" ::: "memory");

            float acc[4][4];
            #pragma unroll
            for (int n = 0; n < 4; n++)
                #pragma unroll
                for (int e = 0; e < 4; e++) acc[n][e] = 0.f;

            const uint32_t bbase = sb + BOFF + (qt & 1) * 16384;
            #pragma unroll
            for (int kc = 0; kc < 4; kc++) {
                #pragma unroll
                for (int kk = 0; kk < 4; kk++) {
                    uint32_t a0, a1, a2, a3;
                    LDSM_X4(a0, a1, a2, a3,
                            aBase + kc * 16384 + (((uint32_t)(kk * 32) + akhi) ^ sxA));
                    uint32_t bq[8];
                    const uint32_t kb = ((uint32_t)(kk * 32) + bkhi) ^ sxB;
                    #pragma unroll
                    for (int p = 0; p < 2; p++)
                        LDSM_X4(bq[p * 4], bq[p * 4 + 1], bq[p * 4 + 2], bq[p * 4 + 3],
                                bbase + kc * 4096 + p * 2048 + brOff + kb);
                    #pragma unroll
                    for (int nt = 0; nt < 4; nt++)
                        MMA16816(acc[nt], a0, a1, a2, a3, bq[nt * 2], bq[nt * 2 + 1]);
                }
            }

            // epilogue
            float scf[4][4];
            float mnA = 1e30f, mnB = 1e30f;
            const int kbase = qt * 32 + 2 * q4;
            #pragma unroll
            for (int nt = 0; nt < 4; nt++) {
                float2 wv = *(const float2*)(swsq + kbase + nt * 8);
                scf[nt][0] = fmaf(-2.f, acc[nt][0], wv.x);
                scf[nt][1] = fmaf(-2.f, acc[nt][1], wv.y);
                scf[nt][2] = fmaf(-2.f, acc[nt][2], wv.x);
                scf[nt][3] = fmaf(-2.f, acc[nt][3], wv.y);
                mnA = fminf(mnA, fminf(scf[nt][0], scf[nt][1]));
                mnB = fminf(mnB, fminf(scf[nt][2], scf[nt][3]));
            }
            mnA = fminf(mnA, __shfl_xor_sync(0xffffffffu, mnA, 1));
            mnA = fminf(mnA, __shfl_xor_sync(0xffffffffu, mnA, 2));
            mnB = fminf(mnB, __shfl_xor_sync(0xffffffffu, mnB, 1));
            mnB = fminf(mnB, __shfl_xor_sync(0xffffffffu, mnB, 2));
            vminA = fminf(vminA, mnA);
            vminB = fminf(vminB, mnB);
            const float thA = vminA + MARGIN_H;
            const float thB = vminB + MARGIN_H;
            #pragma unroll
            for (int nt = 0; nt < 4; nt++) {
                int k0 = kbase + nt * 8;
                if (scf[nt][0] < thA) { int sl = atomicAdd(&scnt[tokA], 1); if (sl < CAP) candp[tokA * CAP + sl] = (uint16_t)k0; }
                if (scf[nt][1] < thA) { int sl = atomicAdd(&scnt[tokA], 1); if (sl < CAP) candp[tokA * CAP + sl] = (uint16_t)(k0 + 1); }
                if (scf[nt][2] < thB) { int sl = atomicAdd(&scnt[tokB], 1); if (sl < CAP) candp[tokB * CAP + sl] = (uint16_t)k0; }
                if (scf[nt][3] < thB) { int sl = atomicAdd(&scnt[tokB], 1); if (sl < CAP) candp[tokB * CAP + sl] = (uint16_t)(k0 + 1); }
            }

            asm volatile("bar.sync 1, 256;" ::: "memory");
            if (qt + 2 < 24) {
                const uint8_t* src = g_whi + ((size_t)(s * 24 + qt + 2)) * 16384 + tid * 16;
                uint32_t dst = sb + BOFF + (qt & 1) * 16384 + tid * 16;
                #pragma unroll
                for (int i = 0; i < 4; i++) CP_ASYNC16(dst + i * 4096, src + i * 4096);
                CP_COMMIT();
            }
        }
    } else {
        // ================= dp4a path: codes 768..1023, 4 qtiles of 64 ======
        asm volatile("cp.async.wait_group 0;" ::: "memory");
        const int w4 = wid - 8;
        const int tg = lid & 3;
        const int cg = lid >> 2;
        const int tbase = w4 * 32 + tg * 8;

        float c2[8], vmin[8];
        #pragma unroll
        for (int i = 0; i < 8; i++) { c2[i] = sxs[tbase + i]; vmin[i] = 1e30f; }

        for (int qt = 0; qt < 4; qt++) {
            int acc[8][8];
            #pragma unroll
            for (int i = 0; i < 8; i++)
                #pragma unroll
                for (int j = 0; j < 8; j++) acc[i][j] = 0;

            const uint32_t wbase = sb + WTO + qt * 16384 + cg * 32;
            #pragma unroll 4
            for (int kc = 0; kc < 64; kc++) {
                uint32_t rot = (uint32_t)((kc & 31) * 16);
                uint32_t arow0 = sb + XTO + kc * 512 + ((tbase * 4 + rot) & 511);
                uint32_t arow1 = sb + XTO + kc * 512 + ((tbase * 4 + rot + 16) & 511);
                uint4 aa, ab, ba, bb;
                LDS128(aa, arow0);
                LDS128(ab, arow1);
                LDS128(ba, wbase + kc * 256);
                LDS128(bb, wbase + kc * 256 + 16);
                uint32_t av[8] = {aa.x, aa.y, aa.z, aa.w, ab.x, ab.y, ab.z, ab.w};
                uint32_t bv[8] = {ba.x, ba.y, ba.z, ba.w, bb.x, bb.y, bb.z, bb.w};
                #pragma unroll
                for (int i = 0; i < 8; i++)
                    #pragma unroll
                    for (int j = 0; j < 8; j++)
                        acc[i][j] = __dp4a((int)av[i], (int)bv[j], acc[i][j]);
            }

            // epilogue: scores + running min + capture
            const int kb = 768 + qt * 64 + cg * 8;
            float wv[8];
            *(float4*)(wv)     = *(const float4*)(swsq + kb);
            *(float4*)(wv + 4) = *(const float4*)(swsq + kb + 4);
            #pragma unroll
            for (int i = 0; i < 8; i++) {
                float sc[8], mn = 1e30f;
                #pragma unroll
                for (int j = 0; j < 8; j++) {
                    sc[j] = fmaf(-c2[i], (float)acc[i][j], wv[j]);
                    mn = fminf(mn, sc[j]);
                }
                mn = fminf(mn, __shfl_xor_sync(0xffffffffu, mn, 4));
                mn = fminf(mn, __shfl_xor_sync(0xffffffffu, mn, 8));
                mn = fminf(mn, __shfl_xor_sync(0xffffffffu, mn, 16));
                vmin[i] = fminf(vmin[i], mn);
                const float th = vmin[i] + MARGIN_D;
                const int tok = tbase + i;
                #pragma unroll
                for (int j = 0; j < 8; j++) {
                    if (sc[j] < th) {
                        int sl = atomicAdd(&scnt[tok], 1);
                        if (sl < CAP) candp[tok * CAP + sl] = (uint16_t)(kb + j);
                    }
                }
            }
        }
    }

    __syncthreads();

    // ---- exact rescore + z write + loss (warps 0-7, 16 tokens each) ----
    if (wid < 8) {
        const float4* W4 = (const float4*)W;
        float4* o4 = (float4*)out;
        float lsum = 0.f;

        for (int tl = 0; tl < 16; tl++) {
            const int tok = wid * 16 + tl;
            const int m   = m0 + tok;
            const int tc  = scnt[tok];

            const float4* xr = h4 + (size_t)m * (Dh / 4) + s * (DSc / 4);
            float4 xa = xr[lid * 2];
            float4 xb = xr[lid * 2 + 1];
            float xs = xa.x * xa.x + xa.y * xa.y + xa.z * xa.z + xa.w * xa.w
                     + xb.x * xb.x + xb.y * xb.y + xb.z * xb.z + xb.w * xb.w;
            #pragma unroll
            for (int o = 16; o > 0; o >>= 1) xs += __shfl_xor_sync(0xffffffffu, xs, o);

            const int ncand = (tc > CAP) ? Kcb : tc;
            float best = 1e30f;
            int   bid  = 0x7fffffff;
            for (int j = 0; j < ncand; j++) {
                const int k = (tc > CAP) ? j : (int)candp[tok * CAP + j];
                const float4* wr = W4 + ((size_t)s * Kcb + k) * (DSc / 4);
                float4 wa = wr[lid * 2];
                float4 wb = wr[lid * 2 + 1];
                float dp = xa.x * wa.x + xa.y * wa.y + xa.z * wa.z + xa.w * wa.w
                         + xb.x * wb.x + xb.y * wb.y + xb.z * wb.z + xb.w * wb.w;
                #pragma unroll
                for (int o = 16; o > 0; o >>= 1) dp += __shfl_xor_sync(0xffffffffu, dp, o);
                float dist = (xs + swsq[k]) - 2.0f * dp;
                if (dist < best || (dist == best && k < bid)) { best = dist; bid = k; }
            }

            if (lid == 0) {
                g_ids[s * BNtok + m] = bid;
                lsum += best;
            }
            const float4* wrw = W4 + ((size_t)s * Kcb + bid) * (DSc / 4);
            float4* orow = o4 + (size_t)m * (Dh / 4) + s * (DSc / 4);
            orow[lid * 2]     = wrw[lid * 2];
            orow[lid * 2 + 1] = wrw[lid * 2 + 1];
        }
        if (lid == 0) atomicAdd(&g_loss, (double)lsum);
    }
}

// ---------------------------------------------------------------------------
__global__ void pack_kernel(float* __restrict__ out) {
    int m = blockIdx.x * 256 + threadIdx.x;
    out[(size_t)BNtok * Dh + m] = (float)(g_ids[m] + Kcb * g_ids[BNtok + m]);
}

__global__ void finalize_kernel(float* __restrict__ out) {
    out[(size_t)BNtok * Dh + BNtok] = (float)(1.25 * g_loss / 16777216.0);
}

// ---------------------------------------------------------------------------
extern "C" void kernel_launch(void* const* d_in, const int* in_sizes, int n_in,
                              void* d_out, int out_size) {
    const float* h = (const float*)d_in[0];
    const float* W = (const float*)d_in[1];
    if (n_in >= 2 && in_sizes[0] == 2 * Kcb * DSc) {  // defensive swap
        const float* tp = h; h = W; W = tp;
    }
    float* out = (float*)d_out;

    cudaFuncSetAttribute(vq_kernel, cudaFuncAttributeMaxDynamicSharedMemorySize, SMEM_SZ);

    prep_kernel<<<256, 256>>>(W);
    vq_kernel<<<1024, 384, SMEM_SZ>>>(h, W, out);

    if (out_size >= BNtok * Dh + BNtok)
        pack_kernel<<<BNtok / 256, 256>>>(out);
    if (out_size >= BNtok * Dh + BNtok + 1)
        finalize_kernel<<<1, 1>>>(out);
}